// round 1
// baseline (speedup 1.0000x reference)
#include <cuda_runtime.h>
#include <cfloat>
#include <cmath>

// Problem shape (fixed for this bench):
//   main_out: (B=32, C=256, H=56, W=56) f32
//   dup_out:  (B=32, K=64,  H=56, W=56) f32
//   min_vals: (C,) f32, max_vals: (C,) f32, vulnerable_idx: (K,) i32
//   out: (B, C, H, W) f32
#define BB 32
#define CC 256
#define HWSZ (56 * 56)          // 3136, divisible by 4
#define HW4 (HWSZ / 4)          // 784
#define TOTAL4 (BB * CC * HW4)  // 6,422,528 float4 elements

// Scratch: inverse map channel -> dup index (-1 if channel not vulnerable).
__device__ int g_inv[CC];

__global__ void build_inv_kernel(const int* __restrict__ vidx, int K) {
    int t = threadIdx.x;
    // init all C entries
    for (int c = t; c < CC; c += blockDim.x) g_inv[c] = -1;
    __syncthreads();
    for (int j = t; j < K; j += blockDim.x) {
        int c = vidx[j];
        if (c >= 0 && c < CC) g_inv[c] = j;
    }
}

__device__ __forceinline__ float fix_nan(float x) {
    // jnp.nan_to_num(x, nan=0.0): nan->0, +inf->FLT_MAX, -inf->-FLT_MAX
    if (isnan(x)) return 0.0f;
    if (isinf(x)) return (x > 0.0f) ? FLT_MAX : -FLT_MAX;
    return x;
}

__device__ __forceinline__ float edac_elem(float m, float d, float lo, float hi) {
    m = fix_nan(m);
    d = fix_nan(d);
    bool mv = (m >= lo) && (m <= hi);
    bool dv = (d >= lo) && (d <= hi);
    if (mv && dv && (m != d)) return fminf(m, d);
    if (dv && !mv) return d;
    return mv ? m : 0.0f;
}

__device__ __forceinline__ float clamp_elem(float m, float lo, float hi) {
    m = fix_nan(m);
    bool mv = (m >= lo) && (m <= hi);
    return mv ? m : 0.0f;
}

__global__ void __launch_bounds__(256) edac_kernel(
    const float4* __restrict__ main4,
    const float4* __restrict__ dup4,
    const float* __restrict__ min_vals,
    const float* __restrict__ max_vals,
    float4* __restrict__ out4,
    int K)
{
    int idx = blockIdx.x * blockDim.x + threadIdx.x;
    if (idx >= TOTAL4) return;

    int plane = idx / HW4;      // b*C + c
    int hw4   = idx - plane * HW4;
    int c     = plane % CC;
    int b     = plane / CC;

    float lo = __ldg(min_vals + c);
    float hi = __ldg(max_vals + c);
    int   j  = g_inv[c];

    float4 m = __ldg(main4 + idx);
    float4 r;

    if (j >= 0) {
        float4 d = __ldg(dup4 + ((long)(b * K + j) * HW4 + hw4));
        r.x = edac_elem(m.x, d.x, lo, hi);
        r.y = edac_elem(m.y, d.y, lo, hi);
        r.z = edac_elem(m.z, d.z, lo, hi);
        r.w = edac_elem(m.w, d.w, lo, hi);
    } else {
        r.x = clamp_elem(m.x, lo, hi);
        r.y = clamp_elem(m.y, lo, hi);
        r.z = clamp_elem(m.z, lo, hi);
        r.w = clamp_elem(m.w, lo, hi);
    }
    out4[idx] = r;
}

extern "C" void kernel_launch(void* const* d_in, const int* in_sizes, int n_in,
                              void* d_out, int out_size) {
    const float* main_out = (const float*)d_in[0];
    const float* dup_out  = (const float*)d_in[1];
    const float* min_vals = (const float*)d_in[2];
    const float* max_vals = (const float*)d_in[3];
    const int*   vidx     = (const int*)d_in[4];
    float* out = (float*)d_out;

    int K = in_sizes[4];

    build_inv_kernel<<<1, 256>>>(vidx, K);

    int threads = 256;
    int blocks = (TOTAL4 + threads - 1) / threads;
    edac_kernel<<<blocks, threads>>>(
        (const float4*)main_out, (const float4*)dup_out,
        min_vals, max_vals, (float4*)out, K);
}

// round 2
// speedup vs baseline: 1.0839x; 1.0839x over previous
#include <cuda_runtime.h>
#include <cfloat>
#include <cmath>

// Shape (fixed): main (32,256,56,56) f32, dup (32,64,56,56) f32,
// min/max (256,), vidx (64,) i32, out (32,256,56,56) f32.
#define BB 32
#define CC 256
#define HWSZ (56 * 56)     // 3136
#define HW4 (HWSZ / 4)     // 784 = 3*256 + 16

__device__ __forceinline__ float fix_nan(float x) {
    if (isnan(x)) return 0.0f;
    if (isinf(x)) return (x > 0.0f) ? FLT_MAX : -FLT_MAX;
    return x;
}

__device__ __forceinline__ float edac_elem(float m, float d, float lo, float hi) {
    m = fix_nan(m);
    d = fix_nan(d);
    bool mv = (m >= lo) && (m <= hi);
    bool dv = (d >= lo) && (d <= hi);
    if (mv && dv && (m != d)) return fminf(m, d);
    if (dv && !mv) return d;
    return mv ? m : 0.0f;
}

__device__ __forceinline__ float clamp_elem(float m, float lo, float hi) {
    m = fix_nan(m);
    return ((m >= lo) && (m <= hi)) ? m : 0.0f;
}

__device__ __forceinline__ float4 edac4(float4 m, float4 d, float lo, float hi) {
    float4 r;
    r.x = edac_elem(m.x, d.x, lo, hi);
    r.y = edac_elem(m.y, d.y, lo, hi);
    r.z = edac_elem(m.z, d.z, lo, hi);
    r.w = edac_elem(m.w, d.w, lo, hi);
    return r;
}

__device__ __forceinline__ float4 clamp4(float4 m, float lo, float hi) {
    float4 r;
    r.x = clamp_elem(m.x, lo, hi);
    r.y = clamp_elem(m.y, lo, hi);
    r.z = clamp_elem(m.z, lo, hi);
    r.w = clamp_elem(m.w, lo, hi);
    return r;
}

// One block per (b, c) plane. grid.x = B*C = 8192, block = 256.
// Each thread handles float4 indices t, t+256, t+512, (t+768 if t<16).
__global__ void __launch_bounds__(256) edac_fused_kernel(
    const float4* __restrict__ main4,
    const float4* __restrict__ dup4,
    const float* __restrict__ min_vals,
    const float* __restrict__ max_vals,
    const int* __restrict__ vidx,
    float4* __restrict__ out4,
    int K)
{
    const int plane = blockIdx.x;
    const int c = plane & (CC - 1);
    const int b = plane >> 8;
    const int t = threadIdx.x;

    __shared__ int s_j;
    if (t == 0) s_j = -1;
    __syncthreads();
    for (int i = t; i < K; i += blockDim.x) {
        if (__ldg(vidx + i) == c) s_j = i;
    }
    __syncthreads();
    const int j = s_j;

    const float lo = __ldg(min_vals + c);
    const float hi = __ldg(max_vals + c);

    const long mbase = (long)plane * HW4;
    const bool tail = (t < HW4 - 3 * 256);   // t < 16

    // Front-batch the main loads (high MLP_p1).
    float4 m0 = __ldg(main4 + mbase + t);
    float4 m1 = __ldg(main4 + mbase + t + 256);
    float4 m2 = __ldg(main4 + mbase + t + 512);
    float4 m3;
    if (tail) m3 = __ldg(main4 + mbase + t + 768);

    if (j >= 0) {
        const long dbase = ((long)(b * K + j)) * HW4;
        float4 d0 = __ldg(dup4 + dbase + t);
        float4 d1 = __ldg(dup4 + dbase + t + 256);
        float4 d2 = __ldg(dup4 + dbase + t + 512);
        float4 d3;
        if (tail) d3 = __ldg(dup4 + dbase + t + 768);

        out4[mbase + t]       = edac4(m0, d0, lo, hi);
        out4[mbase + t + 256] = edac4(m1, d1, lo, hi);
        out4[mbase + t + 512] = edac4(m2, d2, lo, hi);
        if (tail) out4[mbase + t + 768] = edac4(m3, d3, lo, hi);
    } else {
        out4[mbase + t]       = clamp4(m0, lo, hi);
        out4[mbase + t + 256] = clamp4(m1, lo, hi);
        out4[mbase + t + 512] = clamp4(m2, lo, hi);
        if (tail) out4[mbase + t + 768] = clamp4(m3, lo, hi);
    }
}

extern "C" void kernel_launch(void* const* d_in, const int* in_sizes, int n_in,
                              void* d_out, int out_size) {
    const float* main_out = (const float*)d_in[0];
    const float* dup_out  = (const float*)d_in[1];
    const float* min_vals = (const float*)d_in[2];
    const float* max_vals = (const float*)d_in[3];
    const int*   vidx     = (const int*)d_in[4];
    float* out = (float*)d_out;

    int K = in_sizes[4];

    edac_fused_kernel<<<BB * CC, 256>>>(
        (const float4*)main_out, (const float4*)dup_out,
        min_vals, max_vals, vidx, (float4*)out, K);
}